// round 15
// baseline (speedup 1.0000x reference)
#include <cuda_runtime.h>
#include <stdint.h>
#include <math.h>

#define BMAX 8
#define TMAX 4000
#define CN   4
#define DD   256
#define G3   768
#define XW   1536
#define NACT 1024

// ---- device scratch ----
__device__ float g_emb[(size_t)BMAX * TMAX * DD];
__device__ float g_x[(size_t)BMAX * NACT * XW];
__device__ float g_out[(size_t)BMAX * NACT * DD];
__device__ float g_WTproj[DD * DD];
__device__ float g_WiT[DD * XW];
__device__ float g_bicat[XW];
__device__ float g_WhTa[DD * G3];
__device__ float g_WhTm[DD * G3];
__device__ int   g_actlist2[BMAX * CN * NACT];
__device__ int   g_cexcl2[BMAX * CN * TMAX];
__device__ int   g_nact2[BMAX * CN];
__device__ float g_N2[BMAX * CN];
__device__ float g_posN2[BMAX * CN];
__device__ float g_hlast[BMAX * DD];
__device__ float g_hpm[BMAX * G3];
__device__ int   g_sif[BMAX * TMAX];
__device__ int   g_order[BMAX * CN];
__device__ float g_s3[BMAX * NACT];
__device__ unsigned char g_lab3[BMAX * NACT];
__device__ float g_lossS[BMAX], g_lossF[BMAX], g_validF[BMAX], g_posv[BMAX];

// ---- helpers ----
__device__ __forceinline__ float sigmf(float x) {
    if (x >= 0.f) return 1.f / (1.f + expf(-x));
    float e = expf(x);
    return e / (1.f + e);
}
__device__ __forceinline__ float bcef(float p, float y) {
    float lp = logf(p);    if (!(lp > -100.f)) lp = -100.f;
    float lq = log1pf(-p); if (!(lq > -100.f)) lq = -100.f;
    return -(y * lp + (1.f - y) * lq);
}
__device__ __forceinline__ uint32_t smem_u32(const void* p) {
    uint32_t a;
    asm("{ .reg .u64 t; cvta.to.shared.u64 t, %1; cvt.u32.u64 %0, t; }" : "=r"(a) : "l"(p));
    return a;
}
__device__ __forceinline__ uint32_t mapa_sh(uint32_t addr, uint32_t rank) {
    uint32_t r;
    asm volatile("mapa.shared::cluster.u32 %0, %1, %2;" : "=r"(r) : "r"(addr), "r"(rank));
    return r;
}
__device__ __forceinline__ void st_sh_cluster(uint32_t addr, float v) {
    asm volatile("st.shared::cluster.f32 [%0], %1;" :: "r"(addr), "f"(v) : "memory");
}

// ---- prep: transposes + bias concat ----
__global__ void prep_kernel(const float* __restrict__ Wp,
                            const float* __restrict__ Wia, const float* __restrict__ Wim,
                            const float* __restrict__ Wha, const float* __restrict__ Whm,
                            const float* __restrict__ bia, const float* __restrict__ bim) {
    int idx = blockIdx.x * blockDim.x + threadIdx.x;
    int stride = gridDim.x * blockDim.x;
    for (int e = idx; e < DD * DD; e += stride) {
        int i = e / DD, o = e % DD;
        g_WTproj[i * DD + o] = Wp[o * DD + i];
    }
    for (int e = idx; e < DD * XW; e += stride) {
        int i = e / XW, o = e % XW;
        g_WiT[e] = (o < G3) ? Wia[o * DD + i] : Wim[(o - G3) * DD + i];
    }
    for (int e = idx; e < DD * G3; e += stride) {
        int i = e / G3, o = e % G3;
        g_WhTa[e] = Wha[o * DD + i];
        g_WhTm[e] = Whm[o * DD + i];
    }
    for (int e = idx; e < XW; e += stride)
        g_bicat[e] = (e < G3) ? bia[e] : bim[e - G3];
}

// ---- projection (float4 es broadcasts) ----
__global__ __launch_bounds__(256) void proj_kernel(const float* __restrict__ enc,
                                                   const float* __restrict__ bproj, int BT) {
    __shared__ __align__(16) float es[32 * DD];
    int row0 = blockIdx.x * 32;
    int tid = threadIdx.x;
    for (int r = 0; r < 32; r++) {
        int row = row0 + r;
        es[r * DD + tid] = (row < BT) ? enc[(size_t)row * DD + tid] : 0.f;
    }
    __syncthreads();
    int tx = tid & 63, ty = tid >> 6;
    float4 acc[8];
    float4 b4 = ((const float4*)bproj)[tx];
#pragma unroll
    for (int r = 0; r < 8; r++) acc[r] = b4;
    const float4* WT4 = (const float4*)g_WTproj;
    const float4* es4 = (const float4*)es;
#pragma unroll 2
    for (int i = 0; i < DD; i += 4) {
        float4 w0 = WT4[(i    ) * 64 + tx];
        float4 w1 = WT4[(i + 1) * 64 + tx];
        float4 w2 = WT4[(i + 2) * 64 + tx];
        float4 w3 = WT4[(i + 3) * 64 + tx];
#pragma unroll
        for (int r = 0; r < 8; r++) {
            float4 e = es4[(ty * 8 + r) * 64 + (i >> 2)];
            acc[r].x = fmaf(e.x, w0.x, acc[r].x); acc[r].y = fmaf(e.x, w0.y, acc[r].y);
            acc[r].z = fmaf(e.x, w0.z, acc[r].z); acc[r].w = fmaf(e.x, w0.w, acc[r].w);
            acc[r].x = fmaf(e.y, w1.x, acc[r].x); acc[r].y = fmaf(e.y, w1.y, acc[r].y);
            acc[r].z = fmaf(e.y, w1.z, acc[r].z); acc[r].w = fmaf(e.y, w1.w, acc[r].w);
            acc[r].x = fmaf(e.z, w2.x, acc[r].x); acc[r].y = fmaf(e.z, w2.y, acc[r].y);
            acc[r].z = fmaf(e.z, w2.z, acc[r].z); acc[r].w = fmaf(e.z, w2.w, acc[r].w);
            acc[r].x = fmaf(e.w, w3.x, acc[r].x); acc[r].y = fmaf(e.w, w3.y, acc[r].y);
            acc[r].z = fmaf(e.w, w3.z, acc[r].z); acc[r].w = fmaf(e.w, w3.w, acc[r].w);
        }
    }
    for (int r = 0; r < 8; r++) {
        int row = row0 + ty * 8 + r;
        if (row < BT) ((float4*)g_emb)[(size_t)row * 64 + tx] = acc[r];
    }
}

// ---- stats (per batch) ----
__global__ void stats_kernel(const int* __restrict__ label, const int* __restrict__ seq_len,
                             int T, int C) {
    int b = blockIdx.x, tid = threadIdx.x;
    int L = seq_len[b];
    int sum_act = 0, pos = 0;
    int fa[CN] = {0x7fffffff, 0x7fffffff, 0x7fffffff, 0x7fffffff};
    for (int t = tid; t < T; t += 256) {
        const int* lp = &label[((size_t)b * T + t) * C];
        int s = 0;
        for (int c = 0; c < C; c++)
            if (lp[c] > 0) { s++; if (t < fa[c]) fa[c] = t; }
        g_sif[b * T + t] = s;
        sum_act += s;
        if (s > 0 && t < L) pos++;
    }
    __shared__ int sr[256];
    sr[tid] = sum_act; __syncthreads();
    for (int off = 128; off; off >>= 1) { if (tid < off) sr[tid] += sr[tid + off]; __syncthreads(); }
    int tot_act = sr[0]; __syncthreads();
    sr[tid] = pos; __syncthreads();
    for (int off = 128; off; off >>= 1) { if (tid < off) sr[tid] += sr[tid + off]; __syncthreads(); }
    int tot_pos = sr[0]; __syncthreads();
    int fmin[CN];
    for (int c = 0; c < CN; c++) {
        sr[tid] = fa[c]; __syncthreads();
        for (int off = 128; off; off >>= 1) { if (tid < off) sr[tid] = min(sr[tid], sr[tid + off]); __syncthreads(); }
        fmin[c] = sr[0]; __syncthreads();
    }
    if (tid == 0) {
        g_validF[b] = (float)L + (float)tot_act;
        g_posv[b]   = (float)tot_pos;
        int key[CN];
        for (int c = 0; c < CN; c++) key[c] = (fmin[c] == 0x7fffffff) ? (T + 1) : fmin[c];
        bool used[CN] = {false, false, false, false};
        for (int p = 0; p < CN; p++) {
            int best = -1;
            for (int c = 0; c < CN; c++)
                if (!used[c] && (best < 0 || key[c] < key[best])) best = c;
            used[best] = true;
            g_order[b * CN + p] = best;
        }
        g_lossS[b] = 0.f; g_lossF[b] = 0.f;
    }
}

// ---- active list for ALL (b, c) upfront ----
__global__ void actlist_all_kernel(const int* __restrict__ label, const int* __restrict__ seq_len,
                                   int T, int C) {
    int c = blockIdx.x, b = blockIdx.y;
    int m = b * CN + c;
    int tid = threadIdx.x;
    int L = seq_len[b];
    int chunk = (T + 255) / 256;
    int t0 = tid * chunk, t1 = min(t0 + chunk, T);
    int cnt = 0;
    for (int t = t0; t < t1; t++)
        if (label[((size_t)b * T + t) * C + c] > 0) cnt++;
    __shared__ int s[256];
    s[tid] = cnt; __syncthreads();
    for (int off = 1; off < 256; off <<= 1) {
        int v = (tid >= off) ? s[tid - off] : 0;
        __syncthreads(); s[tid] += v; __syncthreads();
    }
    int excl = s[tid] - cnt;
    int total = s[255];
    __syncthreads();
    int c2 = 0, validcnt = 0, poscnt = 0;
    for (int t = t0; t < t1; t++) {
        int ce = excl + c2;
        g_cexcl2[(size_t)m * T + t] = ce;
        bool act = label[((size_t)b * T + t) * C + c] > 0;
        if (t < L && ce >= 1) { validcnt++; if (act) poscnt++; }
        if (act) { int idx = excl + c2; if (idx < NACT) g_actlist2[m * NACT + idx] = t; c2++; }
    }
    s[tid] = validcnt; __syncthreads();
    for (int off = 128; off; off >>= 1) { if (tid < off) s[tid] += s[tid + off]; __syncthreads(); }
    int vt = s[0]; __syncthreads();
    s[tid] = poscnt; __syncthreads();
    for (int off = 128; off; off >>= 1) { if (tid < off) s[tid] += s[tid + off]; __syncthreads(); }
    int pt = s[0];
    if (tid == 0) {
        g_nact2[m]  = min(total, NACT);
        g_N2[m]     = (float)vt;
        g_posN2[m]  = (float)pt;
    }
}

// ---- VAD loss: grid (32, B) ----
__global__ void vad_loss_kernel(const int* __restrict__ seq_len, const float* __restrict__ h0, int T) {
    int b = blockIdx.y;
    int L = seq_len[b];
    int warp = threadIdx.x >> 5, lane = threadIdx.x & 31;
    float Tb = (float)L, pos = g_posv[b];
    const float4* h4 = (const float4*)h0;
    float4 hv0 = h4[lane * 2], hv1 = h4[lane * 2 + 1];
    float acc = 0.f;
    for (int t = blockIdx.x * 8 + warp; t < L; t += 256) {
        const float4* e = (const float4*)&g_emb[((size_t)b * T + t) * DD];
        float4 e0 = e[lane * 2], e1 = e[lane * 2 + 1];
        float s = e0.x*hv0.x + e0.y*hv0.y + e0.z*hv0.z + e0.w*hv0.w
                + e1.x*hv1.x + e1.y*hv1.y + e1.z*hv1.z + e1.w*hv1.w;
        for (int o = 16; o; o >>= 1) s += __shfl_down_sync(0xffffffffu, s, o);
        if (lane == 0) {
            float vlab = (g_sif[b * T + t] > 0) ? 1.f : 0.f;
            float w = (vlab == 1.f) ? Tb / (pos + 1e-9f) : Tb / (Tb - pos + 1e-9f);
            acc += w * bcef(sigmf(s), vlab);
        }
    }
    __shared__ float red[8];
    if (lane == 0) red[warp] = acc;
    __syncthreads();
    if (threadIdx.x == 0) {
        float tot = 0.f;
        for (int w = 0; w < 8; w++) tot += red[w];
        atomicAdd(&g_lossF[b], tot);
    }
}

// ---- xgemm: active rows only (float4 es broadcasts) ----
__global__ __launch_bounds__(256) void xgemm_kernel(int T, int k) {
    int b = blockIdx.z;
    int m = b * CN + g_order[b * CN + k];
    int n = g_nact2[m];
    int j0 = blockIdx.x * 32;
    if (j0 >= n) return;
    __shared__ __align__(16) float es[32 * DD];
    __shared__ int rows[32];
    int tid = threadIdx.x;
    if (tid < 32) {
        int j = j0 + tid;
        rows[tid] = (j < n) ? g_actlist2[m * NACT + j] : -1;
    }
    __syncthreads();
    for (int r = 0; r < 32; r++) {
        int tau = rows[r];
        es[r * DD + tid] = (tau >= 0) ? g_emb[((size_t)b * T + tau) * DD + tid] : 0.f;
    }
    __syncthreads();
    int colBase = blockIdx.y * 256;
    int tx = tid & 63, ty = tid >> 6;
    float4 acc[8];
    float4 b4 = ((const float4*)g_bicat)[colBase / 4 + tx];
#pragma unroll
    for (int r = 0; r < 8; r++) acc[r] = b4;
    const float4* WT4 = (const float4*)g_WiT;
    const float4* es4 = (const float4*)es;
    int wcol = colBase / 4 + tx;
#pragma unroll 2
    for (int i = 0; i < DD; i += 4) {
        float4 w0 = WT4[(i    ) * (XW / 4) + wcol];
        float4 w1 = WT4[(i + 1) * (XW / 4) + wcol];
        float4 w2 = WT4[(i + 2) * (XW / 4) + wcol];
        float4 w3 = WT4[(i + 3) * (XW / 4) + wcol];
#pragma unroll
        for (int r = 0; r < 8; r++) {
            float4 e = es4[(ty * 8 + r) * 64 + (i >> 2)];
            acc[r].x = fmaf(e.x, w0.x, acc[r].x); acc[r].y = fmaf(e.x, w0.y, acc[r].y);
            acc[r].z = fmaf(e.x, w0.z, acc[r].z); acc[r].w = fmaf(e.x, w0.w, acc[r].w);
            acc[r].x = fmaf(e.y, w1.x, acc[r].x); acc[r].y = fmaf(e.y, w1.y, acc[r].y);
            acc[r].z = fmaf(e.y, w1.z, acc[r].z); acc[r].w = fmaf(e.y, w1.w, acc[r].w);
            acc[r].x = fmaf(e.z, w2.x, acc[r].x); acc[r].y = fmaf(e.z, w2.y, acc[r].y);
            acc[r].z = fmaf(e.z, w2.z, acc[r].z); acc[r].w = fmaf(e.z, w2.w, acc[r].w);
            acc[r].x = fmaf(e.w, w3.x, acc[r].x); acc[r].y = fmaf(e.w, w3.y, acc[r].y);
            acc[r].z = fmaf(e.w, w3.z, acc[r].z); acc[r].w = fmaf(e.w, w3.w, acc[r].w);
        }
    }
    for (int r = 0; r < 8; r++) {
        int j = j0 + ty * 8 + r;
        if (j < n)
            ((float4*)g_x)[((size_t)b * NACT + j) * (XW / 4) + wcol] = acc[r];
    }
}

// ---- scan: cluster of 8 CTAs per batch, 384 threads (R14 proven form) ----
__global__ void __cluster_dims__(8, 1, 1) __launch_bounds__(384, 1)
scan_kernel(const float* __restrict__ h0, const float* __restrict__ bha,
            const float* __restrict__ bhm, int k) {
    __shared__ __align__(16) float hbuf[512];   // [2][256]
    __shared__ float accp[384];
    int b = blockIdx.y;
    uint32_t rank;
    asm("mov.u32 %0, %%cluster_ctarank;" : "=r"(rank));
    int base = (int)rank * 32;
    int tid = threadIdx.x;
    int m = b * CN + g_order[b * CN + k];
    int n = g_nact2[m];

    int o = tid % 96, half = tid / 96;        // half in 0..3
    int go = (o >> 5) * 256 + base + (o & 31);

    float wreg[64];
#pragma unroll
    for (int i = 0; i < 64; i++)
        wreg[i] = g_WhTa[(half * 64 + i) * G3 + go];

    if (tid < 256) hbuf[tid] = h0[tid];
    float br = 0.f, bz = 0.f, bn = 0.f;
    if (tid < 32) {
        br = bha[base + tid];
        bz = bha[256 + base + tid];
        bn = bha[512 + base + tid];
    }
    __syncthreads();

    uint32_t hb_addr = smem_u32(hbuf);
    const float* gx = &g_x[(size_t)b * NACT * XW];
    int p = 0;
    for (int j = 0; j < n; j++) {
        float xr = 0.f, xz = 0.f, xn = 0.f;
        if (tid < 32) {
            const float* xp = gx + (size_t)j * XW;
            xr = xp[base + tid];
            xz = xp[256 + base + tid];
            xn = xp[512 + base + tid];
        }
        {
            const float4* hp4 = (const float4*)(hbuf + p * 256 + half * 64);
            float a0 = 0.f, a1 = 0.f;
#pragma unroll
            for (int i4 = 0; i4 < 16; i4++) {
                float4 hv = hp4[i4];
                a0 = fmaf(hv.x, wreg[4 * i4],     a0);
                a1 = fmaf(hv.y, wreg[4 * i4 + 1], a1);
                a0 = fmaf(hv.z, wreg[4 * i4 + 2], a0);
                a1 = fmaf(hv.w, wreg[4 * i4 + 3], a1);
            }
            accp[tid] = a0 + a1;
        }
        __syncthreads();
        if (tid < 32) {
            float ar = br + ((accp[tid]      + accp[96 + tid])  + (accp[192 + tid] + accp[288 + tid]));
            float az = bz + ((accp[32 + tid] + accp[128 + tid]) + (accp[224 + tid] + accp[320 + tid]));
            float an = bn + ((accp[64 + tid] + accp[160 + tid]) + (accp[256 + tid] + accp[352 + tid]));
            float hold = hbuf[p * 256 + base + tid];
            float r  = sigmf(xr + ar);
            float z  = sigmf(xz + az);
            float nn = tanhf(xn + r * an);
            float hnew = (1.f - z) * nn + z * hold;
            g_out[((size_t)b * NACT + j) * DD + base + tid] = hnew;
            uint32_t la = hb_addr + (((p ^ 1) * 256 + base + tid) << 2);
#pragma unroll
            for (uint32_t rr = 0; rr < 8; rr++)
                st_sh_cluster(mapa_sh(la, rr), hnew);
        }
        asm volatile("barrier.cluster.arrive.aligned;" ::: "memory");
        asm volatile("barrier.cluster.wait.aligned;" ::: "memory");
        p ^= 1;
    }
    if (rank == 0 && tid < 256) g_hlast[b * DD + tid] = hbuf[p * 256 + tid];
    {
        const float* hp = hbuf + p * 256 + half * 64;
        float a = 0.f;
#pragma unroll 4
        for (int i = 0; i < 64; i++)
            a = fmaf(hp[i], g_WhTm[(half * 64 + i) * G3 + go], a);
        accp[tid] = a;
    }
    __syncthreads();
    if (tid < 96) {
        int go2 = (tid >> 5) * 256 + base + (tid & 31);
        g_hpm[b * G3 + go2] = bhm[go2] + ((accp[tid] + accp[96 + tid]) + (accp[192 + tid] + accp[288 + tid]));
    }
}

// ---- score loss: grid (32, B) ----
__global__ void score_kernel(const int* __restrict__ label, const int* __restrict__ seq_len,
                             int T, int C, int k) {
    int b = blockIdx.y;
    int L = seq_len[b];
    int warp = threadIdx.x >> 5, lane = threadIdx.x & 31;
    int spk = g_order[b * CN + k];
    int m = b * CN + spk;
    float N = g_N2[m], posN = g_posN2[m];
    float acc = 0.f;
    for (int t = blockIdx.x * 8 + warp; t < L; t += 256) {
        int ce = g_cexcl2[(size_t)m * T + t];
        if (ce < 1) continue;
        const float4* e  = (const float4*)&g_emb[((size_t)b * T + t) * DD];
        const float4* hd = (const float4*)&g_out[((size_t)b * NACT + (ce - 1)) * DD];
        float4 e0 = e[lane * 2], e1 = e[lane * 2 + 1];
        float4 d0 = hd[lane * 2], d1 = hd[lane * 2 + 1];
        float s = e0.x*d0.x + e0.y*d0.y + e0.z*d0.z + e0.w*d0.w
                + e1.x*d1.x + e1.y*d1.y + e1.z*d1.z + e1.w*d1.w;
        for (int o = 16; o; o >>= 1) s += __shfl_down_sync(0xffffffffu, s, o);
        if (lane == 0) {
            float slab = (label[((size_t)b * T + t) * C + spk] > 0) ? 1.f : 0.f;
            float w2 = (slab == 1.f) ? N / (posN + 1e-9f) : N / (N - posN + 1e-9f);
            acc += w2 * bcef(sigmf(s), slab);
        }
    }
    __shared__ float red[8];
    if (lane == 0) red[warp] = acc;
    __syncthreads();
    if (threadIdx.x == 0) {
        float tot = 0.f;
        for (int w = 0; w < 8; w++) tot += red[w];
        if (N > 0.f) atomicAdd(&g_lossS[b], tot / fmaxf(N, 1.f));
    }
}

// ---- upd: GRU one-step rewrite of frame_emb ----
__global__ void upd_kernel(const float* __restrict__ h0, int T, int k) {
    int b = blockIdx.y;
    int m = b * CN + g_order[b * CN + k];
    int j = blockIdx.x;
    if (j >= g_nact2[m]) return;
    int tid = threadIdx.x;
    int tau = g_actlist2[m * NACT + j];
    const float* xp = &g_x[((size_t)b * NACT + j) * XW + G3];
    float xr = xp[tid], xz = xp[DD + tid], xn = xp[2 * DD + tid];
    float hr = g_hpm[b * G3 + tid];
    float hz = g_hpm[b * G3 + DD + tid];
    float hn = g_hpm[b * G3 + 2 * DD + tid];
    float h  = g_hlast[b * DD + tid];
    float r  = sigmf(xr + hr);
    float z  = sigmf(xz + hz);
    float nn = tanhf(xn + r * hn);
    float u  = (1.f - z) * nn + z * h;
    g_emb[((size_t)b * T + tau) * DD + tid] = u;
    __shared__ float red[256];
    red[tid] = u * h0[tid];
    __syncthreads();
    for (int off = 128; off; off >>= 1) { if (tid < off) red[tid] += red[tid + off]; __syncthreads(); }
    if (tid == 0) {
        int sn = g_sif[b * T + tau] - 1;
        g_sif[b * T + tau] = sn;
        g_s3[b * NACT + j] = red[0];
        g_lab3[b * NACT + j] = (sn > 0) ? 1 : 0;
    }
}

// ---- term3 loss ----
__global__ void phase_fin_kernel(int k) {
    int b = blockIdx.x, tid = threadIdx.x;
    int m = b * CN + g_order[b * CN + k];
    int n = g_nact2[m];
    __shared__ float red[256];
    int cnt = 0;
    for (int j = tid; j < n; j += 256) cnt += g_lab3[b * NACT + j];
    red[tid] = (float)cnt; __syncthreads();
    for (int off = 128; off; off >>= 1) { if (tid < off) red[tid] += red[tid + off]; __syncthreads(); }
    float pos3 = red[0];
    float Lb = (float)n;
    __syncthreads();
    float acc = 0.f;
    for (int j = tid; j < n; j += 256) {
        float p = sigmf(g_s3[b * NACT + j]);
        float y = g_lab3[b * NACT + j] ? 1.f : 0.f;
        float w3 = (y == 1.f) ? 1.f : Lb / (Lb - pos3 + 1e-9f);
        acc += w3 * bcef(p, y);
    }
    red[tid] = acc; __syncthreads();
    for (int off = 128; off; off >>= 1) { if (tid < off) red[tid] += red[tid + off]; __syncthreads(); }
    if (tid == 0) g_lossF[b] += red[0];
}

// ---- finalize ----
__global__ void final_kernel(float* __restrict__ out, int B) {
    int b = threadIdx.x;
    if (b < B) {
        out[b]     = g_lossS[b] / (float)CN;
        out[B + b] = g_lossF[b] / (g_validF[b] + 1e-5f);
    }
}

extern "C" void kernel_launch(void* const* d_in, const int* in_sizes, int n_in,
                              void* d_out, int out_size) {
    const float* enc   = (const float*)d_in[0];
    const int*   slen  = (const int*)d_in[1];
    const int*   label = (const int*)d_in[2];
    const float* Wp    = (const float*)d_in[3];
    const float* bp    = (const float*)d_in[4];
    const float* Wia   = (const float*)d_in[5];
    const float* Wha   = (const float*)d_in[6];
    const float* bia   = (const float*)d_in[7];
    const float* bha   = (const float*)d_in[8];
    const float* Wim   = (const float*)d_in[9];
    const float* Whm   = (const float*)d_in[10];
    const float* bim   = (const float*)d_in[11];
    const float* bhm   = (const float*)d_in[12];
    const float* h0    = (const float*)d_in[13];
    float* out = (float*)d_out;

    int B = in_sizes[1];
    int T = in_sizes[0] / (B * DD);
    int C = in_sizes[2] / (B * T);
    int BT = B * T;

    prep_kernel<<<96, 256>>>(Wp, Wia, Wim, Wha, Whm, bia, bim);
    proj_kernel<<<(BT + 31) / 32, 256>>>(enc, bp, BT);
    stats_kernel<<<B, 256>>>(label, slen, T, C);
    actlist_all_kernel<<<dim3(CN, B), 256>>>(label, slen, T, C);
    vad_loss_kernel<<<dim3(32, B), 256>>>(slen, h0, T);

    for (int k = 0; k < CN; k++) {
        xgemm_kernel<<<dim3(NACT / 32, XW / 256, B), 256>>>(T, k);
        scan_kernel<<<dim3(8, B), 384>>>(h0, bha, bhm, k);
        score_kernel<<<dim3(32, B), 256>>>(label, slen, T, C, k);
        upd_kernel<<<dim3(NACT, B), 256>>>(h0, T, k);
        phase_fin_kernel<<<B, 256>>>(k);
    }
    final_kernel<<<1, 32>>>(out, B);
}

// round 16
// speedup vs baseline: 1.1168x; 1.1168x over previous
#include <cuda_runtime.h>
#include <stdint.h>
#include <math.h>

#define BMAX 8
#define TMAX 4000
#define CN   4
#define DD   256
#define G3   768
#define XW   1536
#define NACT 1024

// ---- device scratch ----
__device__ float g_emb[(size_t)BMAX * TMAX * DD];
__device__ float g_x[(size_t)BMAX * NACT * XW];
__device__ float g_out[(size_t)BMAX * NACT * DD];
__device__ float g_WTproj[DD * DD];
__device__ float g_WiT[DD * XW];
__device__ float g_bicat[XW];
__device__ float g_WhTa[DD * G3];
__device__ float g_WhTm[DD * G3];
__device__ int   g_actlist2[BMAX * CN * NACT];
__device__ int   g_cexcl2[BMAX * CN * TMAX];
__device__ int   g_nact2[BMAX * CN];
__device__ float g_N2[BMAX * CN];
__device__ float g_posN2[BMAX * CN];
__device__ float g_hlast[BMAX * DD];
__device__ float g_hpm[BMAX * G3];
__device__ int   g_sif[BMAX * TMAX];
__device__ int   g_order[BMAX * CN];
__device__ float g_s3[BMAX * NACT];
__device__ unsigned char g_lab3[BMAX * NACT];
__device__ float g_lossS[BMAX], g_lossF[BMAX], g_validF[BMAX], g_posv[BMAX];

// ---- helpers ----
__device__ __forceinline__ float sigmf(float x) {
    // fast: __expf/__fdividef, ~1e-6 rel err (vs 1e-3 tolerance)
    return __fdividef(1.f, 1.f + __expf(-x));
}
__device__ __forceinline__ float bcef(float p, float y) {
    float lp = logf(p);    if (!(lp > -100.f)) lp = -100.f;
    float lq = log1pf(-p); if (!(lq > -100.f)) lq = -100.f;
    return -(y * lp + (1.f - y) * lq);
}
__device__ __forceinline__ uint32_t smem_u32(const void* p) {
    uint32_t a;
    asm("{ .reg .u64 t; cvta.to.shared.u64 t, %1; cvt.u32.u64 %0, t; }" : "=r"(a) : "l"(p));
    return a;
}
__device__ __forceinline__ uint32_t mapa_sh(uint32_t addr, uint32_t rank) {
    uint32_t r;
    asm volatile("mapa.shared::cluster.u32 %0, %1, %2;" : "=r"(r) : "r"(addr), "r"(rank));
    return r;
}
__device__ __forceinline__ void st_sh_cluster(uint32_t addr, float v) {
    asm volatile("st.shared::cluster.f32 [%0], %1;" :: "r"(addr), "f"(v) : "memory");
}
__device__ __forceinline__ void cluster_bar() {
    asm volatile("barrier.cluster.arrive.aligned;" ::: "memory");
    asm volatile("barrier.cluster.wait.aligned;" ::: "memory");
}

// ---- prep: transposes + bias concat ----
__global__ void prep_kernel(const float* __restrict__ Wp,
                            const float* __restrict__ Wia, const float* __restrict__ Wim,
                            const float* __restrict__ Wha, const float* __restrict__ Whm,
                            const float* __restrict__ bia, const float* __restrict__ bim) {
    int idx = blockIdx.x * blockDim.x + threadIdx.x;
    int stride = gridDim.x * blockDim.x;
    for (int e = idx; e < DD * DD; e += stride) {
        int i = e / DD, o = e % DD;
        g_WTproj[i * DD + o] = Wp[o * DD + i];
    }
    for (int e = idx; e < DD * XW; e += stride) {
        int i = e / XW, o = e % XW;
        g_WiT[e] = (o < G3) ? Wia[o * DD + i] : Wim[(o - G3) * DD + i];
    }
    for (int e = idx; e < DD * G3; e += stride) {
        int i = e / G3, o = e % G3;
        g_WhTa[e] = Wha[o * DD + i];
        g_WhTm[e] = Whm[o * DD + i];
    }
    for (int e = idx; e < XW; e += stride)
        g_bicat[e] = (e < G3) ? bia[e] : bim[e - G3];
}

// ---- projection (float4 es broadcasts) ----
__global__ __launch_bounds__(256) void proj_kernel(const float* __restrict__ enc,
                                                   const float* __restrict__ bproj, int BT) {
    __shared__ __align__(16) float es[32 * DD];
    int row0 = blockIdx.x * 32;
    int tid = threadIdx.x;
    for (int r = 0; r < 32; r++) {
        int row = row0 + r;
        es[r * DD + tid] = (row < BT) ? enc[(size_t)row * DD + tid] : 0.f;
    }
    __syncthreads();
    int tx = tid & 63, ty = tid >> 6;
    float4 acc[8];
    float4 b4 = ((const float4*)bproj)[tx];
#pragma unroll
    for (int r = 0; r < 8; r++) acc[r] = b4;
    const float4* WT4 = (const float4*)g_WTproj;
    const float4* es4 = (const float4*)es;
#pragma unroll 2
    for (int i = 0; i < DD; i += 4) {
        float4 w0 = WT4[(i    ) * 64 + tx];
        float4 w1 = WT4[(i + 1) * 64 + tx];
        float4 w2 = WT4[(i + 2) * 64 + tx];
        float4 w3 = WT4[(i + 3) * 64 + tx];
#pragma unroll
        for (int r = 0; r < 8; r++) {
            float4 e = es4[(ty * 8 + r) * 64 + (i >> 2)];
            acc[r].x = fmaf(e.x, w0.x, acc[r].x); acc[r].y = fmaf(e.x, w0.y, acc[r].y);
            acc[r].z = fmaf(e.x, w0.z, acc[r].z); acc[r].w = fmaf(e.x, w0.w, acc[r].w);
            acc[r].x = fmaf(e.y, w1.x, acc[r].x); acc[r].y = fmaf(e.y, w1.y, acc[r].y);
            acc[r].z = fmaf(e.y, w1.z, acc[r].z); acc[r].w = fmaf(e.y, w1.w, acc[r].w);
            acc[r].x = fmaf(e.z, w2.x, acc[r].x); acc[r].y = fmaf(e.z, w2.y, acc[r].y);
            acc[r].z = fmaf(e.z, w2.z, acc[r].z); acc[r].w = fmaf(e.z, w2.w, acc[r].w);
            acc[r].x = fmaf(e.w, w3.x, acc[r].x); acc[r].y = fmaf(e.w, w3.y, acc[r].y);
            acc[r].z = fmaf(e.w, w3.z, acc[r].z); acc[r].w = fmaf(e.w, w3.w, acc[r].w);
        }
    }
    for (int r = 0; r < 8; r++) {
        int row = row0 + ty * 8 + r;
        if (row < BT) ((float4*)g_emb)[(size_t)row * 64 + tx] = acc[r];
    }
}

// ---- stats (per batch) ----
__global__ void stats_kernel(const int* __restrict__ label, const int* __restrict__ seq_len,
                             int T, int C) {
    int b = blockIdx.x, tid = threadIdx.x;
    int L = seq_len[b];
    int sum_act = 0, pos = 0;
    int fa[CN] = {0x7fffffff, 0x7fffffff, 0x7fffffff, 0x7fffffff};
    for (int t = tid; t < T; t += 256) {
        const int* lp = &label[((size_t)b * T + t) * C];
        int s = 0;
        for (int c = 0; c < C; c++)
            if (lp[c] > 0) { s++; if (t < fa[c]) fa[c] = t; }
        g_sif[b * T + t] = s;
        sum_act += s;
        if (s > 0 && t < L) pos++;
    }
    __shared__ int sr[256];
    sr[tid] = sum_act; __syncthreads();
    for (int off = 128; off; off >>= 1) { if (tid < off) sr[tid] += sr[tid + off]; __syncthreads(); }
    int tot_act = sr[0]; __syncthreads();
    sr[tid] = pos; __syncthreads();
    for (int off = 128; off; off >>= 1) { if (tid < off) sr[tid] += sr[tid + off]; __syncthreads(); }
    int tot_pos = sr[0]; __syncthreads();
    int fmin[CN];
    for (int c = 0; c < CN; c++) {
        sr[tid] = fa[c]; __syncthreads();
        for (int off = 128; off; off >>= 1) { if (tid < off) sr[tid] = min(sr[tid], sr[tid + off]); __syncthreads(); }
        fmin[c] = sr[0]; __syncthreads();
    }
    if (tid == 0) {
        g_validF[b] = (float)L + (float)tot_act;
        g_posv[b]   = (float)tot_pos;
        int key[CN];
        for (int c = 0; c < CN; c++) key[c] = (fmin[c] == 0x7fffffff) ? (T + 1) : fmin[c];
        bool used[CN] = {false, false, false, false};
        for (int p = 0; p < CN; p++) {
            int best = -1;
            for (int c = 0; c < CN; c++)
                if (!used[c] && (best < 0 || key[c] < key[best])) best = c;
            used[best] = true;
            g_order[b * CN + p] = best;
        }
        g_lossS[b] = 0.f; g_lossF[b] = 0.f;
    }
}

// ---- active list for ALL (b, c) upfront ----
__global__ void actlist_all_kernel(const int* __restrict__ label, const int* __restrict__ seq_len,
                                   int T, int C) {
    int c = blockIdx.x, b = blockIdx.y;
    int m = b * CN + c;
    int tid = threadIdx.x;
    int L = seq_len[b];
    int chunk = (T + 255) / 256;
    int t0 = tid * chunk, t1 = min(t0 + chunk, T);
    int cnt = 0;
    for (int t = t0; t < t1; t++)
        if (label[((size_t)b * T + t) * C + c] > 0) cnt++;
    __shared__ int s[256];
    s[tid] = cnt; __syncthreads();
    for (int off = 1; off < 256; off <<= 1) {
        int v = (tid >= off) ? s[tid - off] : 0;
        __syncthreads(); s[tid] += v; __syncthreads();
    }
    int excl = s[tid] - cnt;
    int total = s[255];
    __syncthreads();
    int c2 = 0, validcnt = 0, poscnt = 0;
    for (int t = t0; t < t1; t++) {
        int ce = excl + c2;
        g_cexcl2[(size_t)m * T + t] = ce;
        bool act = label[((size_t)b * T + t) * C + c] > 0;
        if (t < L && ce >= 1) { validcnt++; if (act) poscnt++; }
        if (act) { int idx = excl + c2; if (idx < NACT) g_actlist2[m * NACT + idx] = t; c2++; }
    }
    s[tid] = validcnt; __syncthreads();
    for (int off = 128; off; off >>= 1) { if (tid < off) s[tid] += s[tid + off]; __syncthreads(); }
    int vt = s[0]; __syncthreads();
    s[tid] = poscnt; __syncthreads();
    for (int off = 128; off; off >>= 1) { if (tid < off) s[tid] += s[tid + off]; __syncthreads(); }
    int pt = s[0];
    if (tid == 0) {
        g_nact2[m]  = min(total, NACT);
        g_N2[m]     = (float)vt;
        g_posN2[m]  = (float)pt;
    }
}

// ---- VAD loss: grid (32, B) ----
__global__ void vad_loss_kernel(const int* __restrict__ seq_len, const float* __restrict__ h0, int T) {
    int b = blockIdx.y;
    int L = seq_len[b];
    int warp = threadIdx.x >> 5, lane = threadIdx.x & 31;
    float Tb = (float)L, pos = g_posv[b];
    const float4* h4 = (const float4*)h0;
    float4 hv0 = h4[lane * 2], hv1 = h4[lane * 2 + 1];
    float acc = 0.f;
    for (int t = blockIdx.x * 8 + warp; t < L; t += 256) {
        const float4* e = (const float4*)&g_emb[((size_t)b * T + t) * DD];
        float4 e0 = e[lane * 2], e1 = e[lane * 2 + 1];
        float s = e0.x*hv0.x + e0.y*hv0.y + e0.z*hv0.z + e0.w*hv0.w
                + e1.x*hv1.x + e1.y*hv1.y + e1.z*hv1.z + e1.w*hv1.w;
        for (int o = 16; o; o >>= 1) s += __shfl_down_sync(0xffffffffu, s, o);
        if (lane == 0) {
            float vlab = (g_sif[b * T + t] > 0) ? 1.f : 0.f;
            float w = (vlab == 1.f) ? Tb / (pos + 1e-9f) : Tb / (Tb - pos + 1e-9f);
            acc += w * bcef(sigmf(s), vlab);
        }
    }
    __shared__ float red[8];
    if (lane == 0) red[warp] = acc;
    __syncthreads();
    if (threadIdx.x == 0) {
        float tot = 0.f;
        for (int w = 0; w < 8; w++) tot += red[w];
        atomicAdd(&g_lossF[b], tot);
    }
}

// ---- xgemm: active rows only (float4 es broadcasts) ----
__global__ __launch_bounds__(256) void xgemm_kernel(int T, int k) {
    int b = blockIdx.z;
    int m = b * CN + g_order[b * CN + k];
    int n = g_nact2[m];
    int j0 = blockIdx.x * 32;
    if (j0 >= n) return;
    __shared__ __align__(16) float es[32 * DD];
    __shared__ int rows[32];
    int tid = threadIdx.x;
    if (tid < 32) {
        int j = j0 + tid;
        rows[tid] = (j < n) ? g_actlist2[m * NACT + j] : -1;
    }
    __syncthreads();
    for (int r = 0; r < 32; r++) {
        int tau = rows[r];
        es[r * DD + tid] = (tau >= 0) ? g_emb[((size_t)b * T + tau) * DD + tid] : 0.f;
    }
    __syncthreads();
    int colBase = blockIdx.y * 256;
    int tx = tid & 63, ty = tid >> 6;
    float4 acc[8];
    float4 b4 = ((const float4*)g_bicat)[colBase / 4 + tx];
#pragma unroll
    for (int r = 0; r < 8; r++) acc[r] = b4;
    const float4* WT4 = (const float4*)g_WiT;
    const float4* es4 = (const float4*)es;
    int wcol = colBase / 4 + tx;
#pragma unroll 2
    for (int i = 0; i < DD; i += 4) {
        float4 w0 = WT4[(i    ) * (XW / 4) + wcol];
        float4 w1 = WT4[(i + 1) * (XW / 4) + wcol];
        float4 w2 = WT4[(i + 2) * (XW / 4) + wcol];
        float4 w3 = WT4[(i + 3) * (XW / 4) + wcol];
#pragma unroll
        for (int r = 0; r < 8; r++) {
            float4 e = es4[(ty * 8 + r) * 64 + (i >> 2)];
            acc[r].x = fmaf(e.x, w0.x, acc[r].x); acc[r].y = fmaf(e.x, w0.y, acc[r].y);
            acc[r].z = fmaf(e.x, w0.z, acc[r].z); acc[r].w = fmaf(e.x, w0.w, acc[r].w);
            acc[r].x = fmaf(e.y, w1.x, acc[r].x); acc[r].y = fmaf(e.y, w1.y, acc[r].y);
            acc[r].z = fmaf(e.y, w1.z, acc[r].z); acc[r].w = fmaf(e.y, w1.w, acc[r].w);
            acc[r].x = fmaf(e.z, w2.x, acc[r].x); acc[r].y = fmaf(e.z, w2.y, acc[r].y);
            acc[r].z = fmaf(e.z, w2.z, acc[r].z); acc[r].w = fmaf(e.z, w2.w, acc[r].w);
            acc[r].x = fmaf(e.w, w3.x, acc[r].x); acc[r].y = fmaf(e.w, w3.y, acc[r].y);
            acc[r].z = fmaf(e.w, w3.z, acc[r].z); acc[r].w = fmaf(e.w, w3.w, acc[r].w);
        }
    }
    for (int r = 0; r < 8; r++) {
        int j = j0 + ty * 8 + r;
        if (j < n)
            ((float4*)g_x)[((size_t)b * NACT + j) * (XW / 4) + wcol] = acc[r];
    }
}

// ---- fused scan + score + upd + fin: cluster of 8 CTAs per batch, 384 threads ----
__global__ void __cluster_dims__(8, 1, 1) __launch_bounds__(384, 1)
scan_fused_kernel(const float* __restrict__ h0, const float* __restrict__ bha,
                  const float* __restrict__ bhm,
                  const int* __restrict__ label, const int* __restrict__ seq_len,
                  int T, int C, int k) {
    __shared__ __align__(16) float hbuf[512];   // [2][256]
    __shared__ float accp[384];
    __shared__ float red12[12];
    __shared__ float sred[8];
    int b = blockIdx.y;
    uint32_t rank;
    asm("mov.u32 %0, %%cluster_ctarank;" : "=r"(rank));
    int base = (int)rank * 32;
    int tid = threadIdx.x;
    int spk = g_order[b * CN + k];
    int m = b * CN + spk;
    int n = g_nact2[m];

    int o = tid % 96, half = tid / 96;        // half in 0..3
    int go = (o >> 5) * 256 + base + (o & 31);

    float wreg[64];
#pragma unroll
    for (int i = 0; i < 64; i++)
        wreg[i] = g_WhTa[(half * 64 + i) * G3 + go];

    if (tid < 256) hbuf[tid] = h0[tid];
    float br = 0.f, bz = 0.f, bn = 0.f;
    if (tid < 32) {
        br = bha[base + tid];
        bz = bha[256 + base + tid];
        bn = bha[512 + base + tid];
    }
    __syncthreads();

    uint32_t hb_addr = smem_u32(hbuf);
    const float* gx = &g_x[(size_t)b * NACT * XW];
    int p = 0;
    for (int j = 0; j < n; j++) {
        float xr = 0.f, xz = 0.f, xn = 0.f;
        if (tid < 32) {
            const float* xp = gx + (size_t)j * XW;
            xr = xp[base + tid];
            xz = xp[256 + base + tid];
            xn = xp[512 + base + tid];
        }
        {
            const float4* hp4 = (const float4*)(hbuf + p * 256 + half * 64);
            float a0 = 0.f, a1 = 0.f;
#pragma unroll
            for (int i4 = 0; i4 < 16; i4++) {
                float4 hv = hp4[i4];
                a0 = fmaf(hv.x, wreg[4 * i4],     a0);
                a1 = fmaf(hv.y, wreg[4 * i4 + 1], a1);
                a0 = fmaf(hv.z, wreg[4 * i4 + 2], a0);
                a1 = fmaf(hv.w, wreg[4 * i4 + 3], a1);
            }
            accp[tid] = a0 + a1;
        }
        __syncthreads();
        if (tid < 32) {
            float ar = br + ((accp[tid]      + accp[96 + tid])  + (accp[192 + tid] + accp[288 + tid]));
            float az = bz + ((accp[32 + tid] + accp[128 + tid]) + (accp[224 + tid] + accp[320 + tid]));
            float an = bn + ((accp[64 + tid] + accp[160 + tid]) + (accp[256 + tid] + accp[352 + tid]));
            float hold = hbuf[p * 256 + base + tid];
            float r  = sigmf(xr + ar);
            float z  = sigmf(xz + az);
            float nn = tanhf(xn + r * an);
            float hnew = (1.f - z) * nn + z * hold;
            g_out[((size_t)b * NACT + j) * DD + base + tid] = hnew;
            uint32_t la = hb_addr + (((p ^ 1) * 256 + base + tid) << 2);
#pragma unroll
            for (uint32_t rr = 0; rr < 8; rr++)
                st_sh_cluster(mapa_sh(la, rr), hnew);
        }
        cluster_bar();
        p ^= 1;
    }
    // hpm / hlast tails
    if (rank == 0 && tid < 256) g_hlast[b * DD + tid] = hbuf[p * 256 + tid];
    {
        const float* hp = hbuf + p * 256 + half * 64;
        float a = 0.f;
#pragma unroll 4
        for (int i = 0; i < 64; i++)
            a = fmaf(hp[i], g_WhTm[(half * 64 + i) * G3 + go], a);
        accp[tid] = a;
    }
    __syncthreads();
    if (tid < 96) {
        int go2 = (tid >> 5) * 256 + base + (tid & 31);
        g_hpm[b * G3 + go2] = bhm[go2] + ((accp[tid] + accp[96 + tid]) + (accp[192 + tid] + accp[288 + tid]));
    }
    __threadfence();
    cluster_bar();

    // ---- fused SCORE (reads g_emb pre-update; 96 warps share t range) ----
    {
        int L = seq_len[b];
        float N = g_N2[m], posN = g_posN2[m];
        int warp = tid >> 5, lane = tid & 31;
        float acc = 0.f;
        for (int t = (int)rank * 12 + warp; t < L; t += 96) {
            int ce = g_cexcl2[(size_t)m * T + t];
            if (ce >= 1) {
                const float4* e  = (const float4*)&g_emb[((size_t)b * T + t) * DD];
                const float4* hd = (const float4*)&g_out[((size_t)b * NACT + (ce - 1)) * DD];
                float4 e0 = e[lane * 2], e1 = e[lane * 2 + 1];
                float4 d0 = hd[lane * 2], d1 = hd[lane * 2 + 1];
                float s = e0.x*d0.x + e0.y*d0.y + e0.z*d0.z + e0.w*d0.w
                        + e1.x*d1.x + e1.y*d1.y + e1.z*d1.z + e1.w*d1.w;
                for (int oo = 16; oo; oo >>= 1) s += __shfl_down_sync(0xffffffffu, s, oo);
                if (lane == 0) {
                    float slab = (label[((size_t)b * T + t) * C + spk] > 0) ? 1.f : 0.f;
                    float w2 = (slab == 1.f) ? N / (posN + 1e-9f) : N / (N - posN + 1e-9f);
                    acc += w2 * bcef(sigmf(s), slab);
                }
            }
        }
        if ((tid & 31) == 0) red12[tid >> 5] = acc;
        __syncthreads();
        if (tid == 0) {
            float tot = 0.f;
            for (int w = 0; w < 12; w++) tot += red12[w];
            if (N > 0.f) atomicAdd(&g_lossS[b], tot / fmaxf(N, 1.f));
        }
    }
    cluster_bar();   // all score reads of g_emb done before upd writes

    // ---- fused UPD (rows striped across ranks) ----
    {
        float hr = 0.f, hz = 0.f, hn2 = 0.f, hh = 0.f, h0v = 0.f;
        if (tid < 256) {
            hr  = g_hpm[b * G3 + tid];
            hz  = g_hpm[b * G3 + DD + tid];
            hn2 = g_hpm[b * G3 + 2 * DD + tid];
            hh  = g_hlast[b * DD + tid];
            h0v = h0[tid];
        }
        for (int j = (int)rank; j < n; j += 8) {
            int tau = -1;
            if (tid < 256) {
                tau = g_actlist2[m * NACT + j];
                const float* xp = &g_x[((size_t)b * NACT + j) * XW + G3];
                float xr2 = xp[tid], xz2 = xp[DD + tid], xn3 = xp[2 * DD + tid];
                float r  = sigmf(xr2 + hr);
                float z  = sigmf(xz2 + hz);
                float nn = tanhf(xn3 + r * hn2);
                float u  = (1.f - z) * nn + z * hh;
                g_emb[((size_t)b * T + tau) * DD + tid] = u;
                float pr = u * h0v;
                for (int oo = 16; oo; oo >>= 1) pr += __shfl_down_sync(0xffffffffu, pr, oo);
                if ((tid & 31) == 0) sred[tid >> 5] = pr;
            }
            __syncthreads();
            if (tid == 0) {
                float dot = 0.f;
                for (int w = 0; w < 8; w++) dot += sred[w];
                int sn = g_sif[b * T + tau] - 1;
                g_sif[b * T + tau] = sn;
                g_s3[b * NACT + j] = dot;
                g_lab3[b * NACT + j] = (sn > 0) ? 1 : 0;
            }
            __syncthreads();
        }
    }
    __threadfence();
    cluster_bar();

    // ---- fused FIN (rank 0 only) ----
    if (rank == 0) {
        int cnt = 0;
        for (int j = tid; j < n; j += 384) cnt += g_lab3[b * NACT + j];
        accp[tid] = (float)cnt;
        __syncthreads();
        if (tid < 128) accp[tid] += accp[tid + 128] + accp[tid + 256];
        __syncthreads();
        for (int off = 64; off; off >>= 1) { if (tid < off) accp[tid] += accp[tid + off]; __syncthreads(); }
        float pos3 = accp[0];
        float Lb = (float)n;
        __syncthreads();
        float acc2 = 0.f;
        for (int j = tid; j < n; j += 384) {
            float pp = sigmf(g_s3[b * NACT + j]);
            float y  = g_lab3[b * NACT + j] ? 1.f : 0.f;
            float w3 = (y == 1.f) ? 1.f : Lb / (Lb - pos3 + 1e-9f);
            acc2 += w3 * bcef(pp, y);
        }
        accp[tid] = acc2;
        __syncthreads();
        if (tid < 128) accp[tid] += accp[tid + 128] + accp[tid + 256];
        __syncthreads();
        for (int off = 64; off; off >>= 1) { if (tid < off) accp[tid] += accp[tid + off]; __syncthreads(); }
        if (tid == 0) g_lossF[b] += accp[0];
    }
    cluster_bar();   // no CTA exits while peers may still target its SMEM
}

// ---- finalize ----
__global__ void final_kernel(float* __restrict__ out, int B) {
    int b = threadIdx.x;
    if (b < B) {
        out[b]     = g_lossS[b] / (float)CN;
        out[B + b] = g_lossF[b] / (g_validF[b] + 1e-5f);
    }
}

extern "C" void kernel_launch(void* const* d_in, const int* in_sizes, int n_in,
                              void* d_out, int out_size) {
    const float* enc   = (const float*)d_in[0];
    const int*   slen  = (const int*)d_in[1];
    const int*   label = (const int*)d_in[2];
    const float* Wp    = (const float*)d_in[3];
    const float* bp    = (const float*)d_in[4];
    const float* Wia   = (const float*)d_in[5];
    const float* Wha   = (const float*)d_in[6];
    const float* bia   = (const float*)d_in[7];
    const float* bha   = (const float*)d_in[8];
    const float* Wim   = (const float*)d_in[9];
    const float* Whm   = (const float*)d_in[10];
    const float* bim   = (const float*)d_in[11];
    const float* bhm   = (const float*)d_in[12];
    const float* h0    = (const float*)d_in[13];
    float* out = (float*)d_out;

    int B = in_sizes[1];
    int T = in_sizes[0] / (B * DD);
    int C = in_sizes[2] / (B * T);
    int BT = B * T;

    prep_kernel<<<96, 256>>>(Wp, Wia, Wim, Wha, Whm, bia, bim);
    proj_kernel<<<(BT + 31) / 32, 256>>>(enc, bp, BT);
    stats_kernel<<<B, 256>>>(label, slen, T, C);
    actlist_all_kernel<<<dim3(CN, B), 256>>>(label, slen, T, C);
    vad_loss_kernel<<<dim3(32, B), 256>>>(slen, h0, T);

    for (int k = 0; k < CN; k++) {
        xgemm_kernel<<<dim3(NACT / 32, XW / 256, B), 256>>>(T, k);
        scan_fused_kernel<<<dim3(8, B), 384>>>(h0, bha, bhm, label, slen, T, C, k);
    }
    final_kernel<<<1, 32>>>(out, B);
}

// round 17
// speedup vs baseline: 1.1195x; 1.0024x over previous
#include <cuda_runtime.h>
#include <stdint.h>
#include <math.h>

#define BMAX 8
#define TMAX 4000
#define CN   4
#define DD   256
#define G3   768
#define XW   1536
#define NACT 1024

// ---- device scratch ----
__device__ float g_emb[(size_t)BMAX * TMAX * DD];
__device__ float g_x[(size_t)BMAX * NACT * XW];
__device__ float g_out[(size_t)BMAX * NACT * DD];
__device__ float g_WTproj[DD * DD];
__device__ float g_WiT[DD * XW];
__device__ float g_bicat[XW];
__device__ float g_WhTa[DD * G3];
__device__ float g_WhTm[DD * G3];
__device__ int   g_actlist2[BMAX * CN * NACT];
__device__ int   g_cexcl2[BMAX * CN * TMAX];
__device__ int   g_nact2[BMAX * CN];
__device__ float g_N2[BMAX * CN];
__device__ float g_posN2[BMAX * CN];
__device__ float g_hlast[BMAX * DD];
__device__ float g_hpm[BMAX * G3];
__device__ int   g_sif[BMAX * TMAX];
__device__ int   g_order[BMAX * CN];
__device__ float g_s3[BMAX * NACT];
__device__ unsigned char g_lab3[BMAX * NACT];
__device__ float g_lossS[BMAX], g_lossF[BMAX], g_validF[BMAX], g_posv[BMAX];

// ---- helpers ----
__device__ __forceinline__ float sigmf(float x) {
    return __fdividef(1.f, 1.f + __expf(-x));
}
__device__ __forceinline__ float tanhf_fast(float x) {
    // 2*sigmoid(2x)-1; saturates correctly at +/-inf; ~1e-6 rel err
    return __fdividef(2.f, 1.f + __expf(-2.f * x)) - 1.f;
}
__device__ __forceinline__ float bcef(float p, float y) {
    float lp = logf(p);    if (!(lp > -100.f)) lp = -100.f;
    float lq = log1pf(-p); if (!(lq > -100.f)) lq = -100.f;
    return -(y * lp + (1.f - y) * lq);
}
__device__ __forceinline__ uint32_t smem_u32(const void* p) {
    uint32_t a;
    asm("{ .reg .u64 t; cvta.to.shared.u64 t, %1; cvt.u32.u64 %0, t; }" : "=r"(a) : "l"(p));
    return a;
}
__device__ __forceinline__ uint32_t mapa_sh(uint32_t addr, uint32_t rank) {
    uint32_t r;
    asm volatile("mapa.shared::cluster.u32 %0, %1, %2;" : "=r"(r) : "r"(addr), "r"(rank));
    return r;
}
__device__ __forceinline__ void st_sh_cluster(uint32_t addr, float v) {
    asm volatile("st.shared::cluster.f32 [%0], %1;" :: "r"(addr), "f"(v) : "memory");
}
__device__ __forceinline__ void cluster_bar() {
    asm volatile("barrier.cluster.arrive.aligned;" ::: "memory");
    asm volatile("barrier.cluster.wait.aligned;" ::: "memory");
}

// ---- prep: transposes + bias concat ----
__global__ void prep_kernel(const float* __restrict__ Wp,
                            const float* __restrict__ Wia, const float* __restrict__ Wim,
                            const float* __restrict__ Wha, const float* __restrict__ Whm,
                            const float* __restrict__ bia, const float* __restrict__ bim) {
    int idx = blockIdx.x * blockDim.x + threadIdx.x;
    int stride = gridDim.x * blockDim.x;
    for (int e = idx; e < DD * DD; e += stride) {
        int i = e / DD, o = e % DD;
        g_WTproj[i * DD + o] = Wp[o * DD + i];
    }
    for (int e = idx; e < DD * XW; e += stride) {
        int i = e / XW, o = e % XW;
        g_WiT[e] = (o < G3) ? Wia[o * DD + i] : Wim[(o - G3) * DD + i];
    }
    for (int e = idx; e < DD * G3; e += stride) {
        int i = e / G3, o = e % G3;
        g_WhTa[e] = Wha[o * DD + i];
        g_WhTm[e] = Whm[o * DD + i];
    }
    for (int e = idx; e < XW; e += stride)
        g_bicat[e] = (e < G3) ? bia[e] : bim[e - G3];
}

// ---- projection (float4 es broadcasts) ----
__global__ __launch_bounds__(256) void proj_kernel(const float* __restrict__ enc,
                                                   const float* __restrict__ bproj, int BT) {
    __shared__ __align__(16) float es[32 * DD];
    int row0 = blockIdx.x * 32;
    int tid = threadIdx.x;
    for (int r = 0; r < 32; r++) {
        int row = row0 + r;
        es[r * DD + tid] = (row < BT) ? enc[(size_t)row * DD + tid] : 0.f;
    }
    __syncthreads();
    int tx = tid & 63, ty = tid >> 6;
    float4 acc[8];
    float4 b4 = ((const float4*)bproj)[tx];
#pragma unroll
    for (int r = 0; r < 8; r++) acc[r] = b4;
    const float4* WT4 = (const float4*)g_WTproj;
    const float4* es4 = (const float4*)es;
#pragma unroll 2
    for (int i = 0; i < DD; i += 4) {
        float4 w0 = WT4[(i    ) * 64 + tx];
        float4 w1 = WT4[(i + 1) * 64 + tx];
        float4 w2 = WT4[(i + 2) * 64 + tx];
        float4 w3 = WT4[(i + 3) * 64 + tx];
#pragma unroll
        for (int r = 0; r < 8; r++) {
            float4 e = es4[(ty * 8 + r) * 64 + (i >> 2)];
            acc[r].x = fmaf(e.x, w0.x, acc[r].x); acc[r].y = fmaf(e.x, w0.y, acc[r].y);
            acc[r].z = fmaf(e.x, w0.z, acc[r].z); acc[r].w = fmaf(e.x, w0.w, acc[r].w);
            acc[r].x = fmaf(e.y, w1.x, acc[r].x); acc[r].y = fmaf(e.y, w1.y, acc[r].y);
            acc[r].z = fmaf(e.y, w1.z, acc[r].z); acc[r].w = fmaf(e.y, w1.w, acc[r].w);
            acc[r].x = fmaf(e.z, w2.x, acc[r].x); acc[r].y = fmaf(e.z, w2.y, acc[r].y);
            acc[r].z = fmaf(e.z, w2.z, acc[r].z); acc[r].w = fmaf(e.z, w2.w, acc[r].w);
            acc[r].x = fmaf(e.w, w3.x, acc[r].x); acc[r].y = fmaf(e.w, w3.y, acc[r].y);
            acc[r].z = fmaf(e.w, w3.z, acc[r].z); acc[r].w = fmaf(e.w, w3.w, acc[r].w);
        }
    }
    for (int r = 0; r < 8; r++) {
        int row = row0 + ty * 8 + r;
        if (row < BT) ((float4*)g_emb)[(size_t)row * 64 + tx] = acc[r];
    }
}

// ---- stats (per batch) ----
__global__ void stats_kernel(const int* __restrict__ label, const int* __restrict__ seq_len,
                             int T, int C) {
    int b = blockIdx.x, tid = threadIdx.x;
    int L = seq_len[b];
    int sum_act = 0, pos = 0;
    int fa[CN] = {0x7fffffff, 0x7fffffff, 0x7fffffff, 0x7fffffff};
    for (int t = tid; t < T; t += 256) {
        const int* lp = &label[((size_t)b * T + t) * C];
        int s = 0;
        for (int c = 0; c < C; c++)
            if (lp[c] > 0) { s++; if (t < fa[c]) fa[c] = t; }
        g_sif[b * T + t] = s;
        sum_act += s;
        if (s > 0 && t < L) pos++;
    }
    __shared__ int sr[256];
    sr[tid] = sum_act; __syncthreads();
    for (int off = 128; off; off >>= 1) { if (tid < off) sr[tid] += sr[tid + off]; __syncthreads(); }
    int tot_act = sr[0]; __syncthreads();
    sr[tid] = pos; __syncthreads();
    for (int off = 128; off; off >>= 1) { if (tid < off) sr[tid] += sr[tid + off]; __syncthreads(); }
    int tot_pos = sr[0]; __syncthreads();
    int fmin[CN];
    for (int c = 0; c < CN; c++) {
        sr[tid] = fa[c]; __syncthreads();
        for (int off = 128; off; off >>= 1) { if (tid < off) sr[tid] = min(sr[tid], sr[tid + off]); __syncthreads(); }
        fmin[c] = sr[0]; __syncthreads();
    }
    if (tid == 0) {
        g_validF[b] = (float)L + (float)tot_act;
        g_posv[b]   = (float)tot_pos;
        int key[CN];
        for (int c = 0; c < CN; c++) key[c] = (fmin[c] == 0x7fffffff) ? (T + 1) : fmin[c];
        bool used[CN] = {false, false, false, false};
        for (int p = 0; p < CN; p++) {
            int best = -1;
            for (int c = 0; c < CN; c++)
                if (!used[c] && (best < 0 || key[c] < key[best])) best = c;
            used[best] = true;
            g_order[b * CN + p] = best;
        }
        g_lossS[b] = 0.f; g_lossF[b] = 0.f;
    }
}

// ---- active list for ALL (b, c) upfront ----
__global__ void actlist_all_kernel(const int* __restrict__ label, const int* __restrict__ seq_len,
                                   int T, int C) {
    int c = blockIdx.x, b = blockIdx.y;
    int m = b * CN + c;
    int tid = threadIdx.x;
    int L = seq_len[b];
    int chunk = (T + 255) / 256;
    int t0 = tid * chunk, t1 = min(t0 + chunk, T);
    int cnt = 0;
    for (int t = t0; t < t1; t++)
        if (label[((size_t)b * T + t) * C + c] > 0) cnt++;
    __shared__ int s[256];
    s[tid] = cnt; __syncthreads();
    for (int off = 1; off < 256; off <<= 1) {
        int v = (tid >= off) ? s[tid - off] : 0;
        __syncthreads(); s[tid] += v; __syncthreads();
    }
    int excl = s[tid] - cnt;
    int total = s[255];
    __syncthreads();
    int c2 = 0, validcnt = 0, poscnt = 0;
    for (int t = t0; t < t1; t++) {
        int ce = excl + c2;
        g_cexcl2[(size_t)m * T + t] = ce;
        bool act = label[((size_t)b * T + t) * C + c] > 0;
        if (t < L && ce >= 1) { validcnt++; if (act) poscnt++; }
        if (act) { int idx = excl + c2; if (idx < NACT) g_actlist2[m * NACT + idx] = t; c2++; }
    }
    s[tid] = validcnt; __syncthreads();
    for (int off = 128; off; off >>= 1) { if (tid < off) s[tid] += s[tid + off]; __syncthreads(); }
    int vt = s[0]; __syncthreads();
    s[tid] = poscnt; __syncthreads();
    for (int off = 128; off; off >>= 1) { if (tid < off) s[tid] += s[tid + off]; __syncthreads(); }
    int pt = s[0];
    if (tid == 0) {
        g_nact2[m]  = min(total, NACT);
        g_N2[m]     = (float)vt;
        g_posN2[m]  = (float)pt;
    }
}

// ---- VAD loss: grid (32, B) ----
__global__ void vad_loss_kernel(const int* __restrict__ seq_len, const float* __restrict__ h0, int T) {
    int b = blockIdx.y;
    int L = seq_len[b];
    int warp = threadIdx.x >> 5, lane = threadIdx.x & 31;
    float Tb = (float)L, pos = g_posv[b];
    const float4* h4 = (const float4*)h0;
    float4 hv0 = h4[lane * 2], hv1 = h4[lane * 2 + 1];
    float acc = 0.f;
    for (int t = blockIdx.x * 8 + warp; t < L; t += 256) {
        const float4* e = (const float4*)&g_emb[((size_t)b * T + t) * DD];
        float4 e0 = e[lane * 2], e1 = e[lane * 2 + 1];
        float s = e0.x*hv0.x + e0.y*hv0.y + e0.z*hv0.z + e0.w*hv0.w
                + e1.x*hv1.x + e1.y*hv1.y + e1.z*hv1.z + e1.w*hv1.w;
        for (int o = 16; o; o >>= 1) s += __shfl_down_sync(0xffffffffu, s, o);
        if (lane == 0) {
            float vlab = (g_sif[b * T + t] > 0) ? 1.f : 0.f;
            float w = (vlab == 1.f) ? Tb / (pos + 1e-9f) : Tb / (Tb - pos + 1e-9f);
            acc += w * bcef(sigmf(s), vlab);
        }
    }
    __shared__ float red[8];
    if (lane == 0) red[warp] = acc;
    __syncthreads();
    if (threadIdx.x == 0) {
        float tot = 0.f;
        for (int w = 0; w < 8; w++) tot += red[w];
        atomicAdd(&g_lossF[b], tot);
    }
}

// ---- xgemm: active rows only (float4 es broadcasts) ----
__global__ __launch_bounds__(256) void xgemm_kernel(int T, int k) {
    int b = blockIdx.z;
    int m = b * CN + g_order[b * CN + k];
    int n = g_nact2[m];
    int j0 = blockIdx.x * 32;
    if (j0 >= n) return;
    __shared__ __align__(16) float es[32 * DD];
    __shared__ int rows[32];
    int tid = threadIdx.x;
    if (tid < 32) {
        int j = j0 + tid;
        rows[tid] = (j < n) ? g_actlist2[m * NACT + j] : -1;
    }
    __syncthreads();
    for (int r = 0; r < 32; r++) {
        int tau = rows[r];
        es[r * DD + tid] = (tau >= 0) ? g_emb[((size_t)b * T + tau) * DD + tid] : 0.f;
    }
    __syncthreads();
    int colBase = blockIdx.y * 256;
    int tx = tid & 63, ty = tid >> 6;
    float4 acc[8];
    float4 b4 = ((const float4*)g_bicat)[colBase / 4 + tx];
#pragma unroll
    for (int r = 0; r < 8; r++) acc[r] = b4;
    const float4* WT4 = (const float4*)g_WiT;
    const float4* es4 = (const float4*)es;
    int wcol = colBase / 4 + tx;
#pragma unroll 2
    for (int i = 0; i < DD; i += 4) {
        float4 w0 = WT4[(i    ) * (XW / 4) + wcol];
        float4 w1 = WT4[(i + 1) * (XW / 4) + wcol];
        float4 w2 = WT4[(i + 2) * (XW / 4) + wcol];
        float4 w3 = WT4[(i + 3) * (XW / 4) + wcol];
#pragma unroll
        for (int r = 0; r < 8; r++) {
            float4 e = es4[(ty * 8 + r) * 64 + (i >> 2)];
            acc[r].x = fmaf(e.x, w0.x, acc[r].x); acc[r].y = fmaf(e.x, w0.y, acc[r].y);
            acc[r].z = fmaf(e.x, w0.z, acc[r].z); acc[r].w = fmaf(e.x, w0.w, acc[r].w);
            acc[r].x = fmaf(e.y, w1.x, acc[r].x); acc[r].y = fmaf(e.y, w1.y, acc[r].y);
            acc[r].z = fmaf(e.y, w1.z, acc[r].z); acc[r].w = fmaf(e.y, w1.w, acc[r].w);
            acc[r].x = fmaf(e.z, w2.x, acc[r].x); acc[r].y = fmaf(e.z, w2.y, acc[r].y);
            acc[r].z = fmaf(e.z, w2.z, acc[r].z); acc[r].w = fmaf(e.z, w2.w, acc[r].w);
            acc[r].x = fmaf(e.w, w3.x, acc[r].x); acc[r].y = fmaf(e.w, w3.y, acc[r].y);
            acc[r].z = fmaf(e.w, w3.z, acc[r].z); acc[r].w = fmaf(e.w, w3.w, acc[r].w);
        }
    }
    for (int r = 0; r < 8; r++) {
        int j = j0 + ty * 8 + r;
        if (j < n)
            ((float4*)g_x)[((size_t)b * NACT + j) * (XW / 4) + wcol] = acc[r];
    }
}

// ---- fused scan + score + upd + fin: cluster of 8 CTAs per batch, 384 threads ----
__global__ void __cluster_dims__(8, 1, 1) __launch_bounds__(384, 1)
scan_fused_kernel(const float* __restrict__ h0, const float* __restrict__ bha,
                  const float* __restrict__ bhm,
                  const int* __restrict__ label, const int* __restrict__ seq_len,
                  int T, int C, int k) {
    __shared__ __align__(16) float hbuf[512];   // [2][256]
    __shared__ float accp[384];
    __shared__ float red12[12];
    __shared__ float sred[8];
    int b = blockIdx.y;
    uint32_t rank;
    asm("mov.u32 %0, %%cluster_ctarank;" : "=r"(rank));
    int base = (int)rank * 32;
    int tid = threadIdx.x;
    int spk = g_order[b * CN + k];
    int m = b * CN + spk;
    int n = g_nact2[m];

    int o = tid % 96, half = tid / 96;        // half in 0..3
    int go = (o >> 5) * 256 + base + (o & 31);

    float wreg[64];
#pragma unroll
    for (int i = 0; i < 64; i++)
        wreg[i] = g_WhTa[(half * 64 + i) * G3 + go];

    if (tid < 256) hbuf[tid] = h0[tid];
    float br = 0.f, bz = 0.f, bn = 0.f;
    if (tid < 32) {
        br = bha[base + tid];
        bz = bha[256 + base + tid];
        bn = bha[512 + base + tid];
    }
    __syncthreads();

    uint32_t hb_addr = smem_u32(hbuf);
    const float* gx = &g_x[(size_t)b * NACT * XW];
    int p = 0;
    // prefetch x[0]
    float xr = 0.f, xz = 0.f, xn = 0.f;
    if (tid < 32 && n > 0) {
        xr = gx[base + tid];
        xz = gx[256 + base + tid];
        xn = gx[512 + base + tid];
    }
    for (int j = 0; j < n; j++) {
        {
            const float4* hp4 = (const float4*)(hbuf + p * 256 + half * 64);
            float a0 = 0.f, a1 = 0.f;
#pragma unroll
            for (int i4 = 0; i4 < 16; i4++) {
                float4 hv = hp4[i4];
                a0 = fmaf(hv.x, wreg[4 * i4],     a0);
                a1 = fmaf(hv.y, wreg[4 * i4 + 1], a1);
                a0 = fmaf(hv.z, wreg[4 * i4 + 2], a0);
                a1 = fmaf(hv.w, wreg[4 * i4 + 3], a1);
            }
            accp[tid] = a0 + a1;
        }
        __syncthreads();
        float nxr = 0.f, nxz = 0.f, nxn = 0.f;
        if (tid < 32) {
            // prefetch x[j+1] (overlaps GRU compute + DSMEM broadcast + barrier)
            if (j + 1 < n) {
                const float* xq = gx + (size_t)(j + 1) * XW;
                nxr = xq[base + tid];
                nxz = xq[256 + base + tid];
                nxn = xq[512 + base + tid];
            }
            float ar = br + ((accp[tid]      + accp[96 + tid])  + (accp[192 + tid] + accp[288 + tid]));
            float az = bz + ((accp[32 + tid] + accp[128 + tid]) + (accp[224 + tid] + accp[320 + tid]));
            float an = bn + ((accp[64 + tid] + accp[160 + tid]) + (accp[256 + tid] + accp[352 + tid]));
            float hold = hbuf[p * 256 + base + tid];
            float r  = sigmf(xr + ar);
            float z  = sigmf(xz + az);
            float nn = tanhf_fast(xn + r * an);
            float hnew = (1.f - z) * nn + z * hold;
            g_out[((size_t)b * NACT + j) * DD + base + tid] = hnew;
            uint32_t la = hb_addr + (((p ^ 1) * 256 + base + tid) << 2);
#pragma unroll
            for (uint32_t rr = 0; rr < 8; rr++)
                st_sh_cluster(mapa_sh(la, rr), hnew);
        }
        cluster_bar();
        xr = nxr; xz = nxz; xn = nxn;
        p ^= 1;
    }
    // hpm / hlast tails
    if (rank == 0 && tid < 256) g_hlast[b * DD + tid] = hbuf[p * 256 + tid];
    {
        const float* hp = hbuf + p * 256 + half * 64;
        float a = 0.f;
#pragma unroll 4
        for (int i = 0; i < 64; i++)
            a = fmaf(hp[i], g_WhTm[(half * 64 + i) * G3 + go], a);
        accp[tid] = a;
    }
    __syncthreads();
    if (tid < 96) {
        int go2 = (tid >> 5) * 256 + base + (tid & 31);
        g_hpm[b * G3 + go2] = bhm[go2] + ((accp[tid] + accp[96 + tid]) + (accp[192 + tid] + accp[288 + tid]));
    }
    __threadfence();
    cluster_bar();

    // ---- fused SCORE (reads g_emb pre-update; 96 warps share t range) ----
    {
        int L = seq_len[b];
        float N = g_N2[m], posN = g_posN2[m];
        int warp = tid >> 5, lane = tid & 31;
        float acc = 0.f;
        for (int t = (int)rank * 12 + warp; t < L; t += 96) {
            int ce = g_cexcl2[(size_t)m * T + t];
            if (ce >= 1) {
                const float4* e  = (const float4*)&g_emb[((size_t)b * T + t) * DD];
                const float4* hd = (const float4*)&g_out[((size_t)b * NACT + (ce - 1)) * DD];
                float4 e0 = e[lane * 2], e1 = e[lane * 2 + 1];
                float4 d0 = hd[lane * 2], d1 = hd[lane * 2 + 1];
                float s = e0.x*d0.x + e0.y*d0.y + e0.z*d0.z + e0.w*d0.w
                        + e1.x*d1.x + e1.y*d1.y + e1.z*d1.z + e1.w*d1.w;
                for (int oo = 16; oo; oo >>= 1) s += __shfl_down_sync(0xffffffffu, s, oo);
                if (lane == 0) {
                    float slab = (label[((size_t)b * T + t) * C + spk] > 0) ? 1.f : 0.f;
                    float w2 = (slab == 1.f) ? N / (posN + 1e-9f) : N / (N - posN + 1e-9f);
                    acc += w2 * bcef(sigmf(s), slab);
                }
            }
        }
        if ((tid & 31) == 0) red12[tid >> 5] = acc;
        __syncthreads();
        if (tid == 0) {
            float tot = 0.f;
            for (int w = 0; w < 12; w++) tot += red12[w];
            if (N > 0.f) atomicAdd(&g_lossS[b], tot / fmaxf(N, 1.f));
        }
    }
    cluster_bar();   // all score reads of g_emb done before upd writes

    // ---- fused UPD (rows striped across ranks) ----
    {
        float hr = 0.f, hz = 0.f, hn2 = 0.f, hh = 0.f, h0v = 0.f;
        if (tid < 256) {
            hr  = g_hpm[b * G3 + tid];
            hz  = g_hpm[b * G3 + DD + tid];
            hn2 = g_hpm[b * G3 + 2 * DD + tid];
            hh  = g_hlast[b * DD + tid];
            h0v = h0[tid];
        }
        for (int j = (int)rank; j < n; j += 8) {
            int tau = -1;
            if (tid < 256) {
                tau = g_actlist2[m * NACT + j];
                const float* xp = &g_x[((size_t)b * NACT + j) * XW + G3];
                float xr2 = xp[tid], xz2 = xp[DD + tid], xn3 = xp[2 * DD + tid];
                float r  = sigmf(xr2 + hr);
                float z  = sigmf(xz2 + hz);
                float nn = tanhf_fast(xn3 + r * hn2);
                float u  = (1.f - z) * nn + z * hh;
                g_emb[((size_t)b * T + tau) * DD + tid] = u;
                float pr = u * h0v;
                for (int oo = 16; oo; oo >>= 1) pr += __shfl_down_sync(0xffffffffu, pr, oo);
                if ((tid & 31) == 0) sred[tid >> 5] = pr;
            }
            __syncthreads();
            if (tid == 0) {
                float dot = 0.f;
                for (int w = 0; w < 8; w++) dot += sred[w];
                int sn = g_sif[b * T + tau] - 1;
                g_sif[b * T + tau] = sn;
                g_s3[b * NACT + j] = dot;
                g_lab3[b * NACT + j] = (sn > 0) ? 1 : 0;
            }
            __syncthreads();
        }
    }
    __threadfence();
    cluster_bar();

    // ---- fused FIN (rank 0 only) ----
    if (rank == 0) {
        int cnt = 0;
        for (int j = tid; j < n; j += 384) cnt += g_lab3[b * NACT + j];
        accp[tid] = (float)cnt;
        __syncthreads();
        if (tid < 128) accp[tid] += accp[tid + 128] + accp[tid + 256];
        __syncthreads();
        for (int off = 64; off; off >>= 1) { if (tid < off) accp[tid] += accp[tid + off]; __syncthreads(); }
        float pos3 = accp[0];
        float Lb = (float)n;
        __syncthreads();
        float acc2 = 0.f;
        for (int j = tid; j < n; j += 384) {
            float pp = sigmf(g_s3[b * NACT + j]);
            float y  = g_lab3[b * NACT + j] ? 1.f : 0.f;
            float w3 = (y == 1.f) ? 1.f : Lb / (Lb - pos3 + 1e-9f);
            acc2 += w3 * bcef(pp, y);
        }
        accp[tid] = acc2;
        __syncthreads();
        if (tid < 128) accp[tid] += accp[tid + 128] + accp[tid + 256];
        __syncthreads();
        for (int off = 64; off; off >>= 1) { if (tid < off) accp[tid] += accp[tid + off]; __syncthreads(); }
        if (tid == 0) g_lossF[b] += accp[0];
    }
    cluster_bar();   // no CTA exits while peers may still target its SMEM
}

// ---- finalize ----
__global__ void final_kernel(float* __restrict__ out, int B) {
    int b = threadIdx.x;
    if (b < B) {
        out[b]     = g_lossS[b] / (float)CN;
        out[B + b] = g_lossF[b] / (g_validF[b] + 1e-5f);
    }
}

extern "C" void kernel_launch(void* const* d_in, const int* in_sizes, int n_in,
                              void* d_out, int out_size) {
    const float* enc   = (const float*)d_in[0];
    const int*   slen  = (const int*)d_in[1];
    const int*   label = (const int*)d_in[2];
    const float* Wp    = (const float*)d_in[3];
    const float* bp    = (const float*)d_in[4];
    const float* Wia   = (const float*)d_in[5];
    const float* Wha   = (const float*)d_in[6];
    const float* bia   = (const float*)d_in[7];
    const float* bha   = (const float*)d_in[8];
    const float* Wim   = (const float*)d_in[9];
    const float* Whm   = (const float*)d_in[10];
    const float* bim   = (const float*)d_in[11];
    const float* bhm   = (const float*)d_in[12];
    const float* h0    = (const float*)d_in[13];
    float* out = (float*)d_out;

    int B = in_sizes[1];
    int T = in_sizes[0] / (B * DD);
    int C = in_sizes[2] / (B * T);
    int BT = B * T;

    prep_kernel<<<96, 256>>>(Wp, Wia, Wim, Wha, Whm, bia, bim);
    proj_kernel<<<(BT + 31) / 32, 256>>>(enc, bp, BT);
    stats_kernel<<<B, 256>>>(label, slen, T, C);
    actlist_all_kernel<<<dim3(CN, B), 256>>>(label, slen, T, C);
    vad_loss_kernel<<<dim3(32, B), 256>>>(slen, h0, T);

    for (int k = 0; k < CN; k++) {
        xgemm_kernel<<<dim3(NACT / 32, XW / 256, B), 256>>>(T, k);
        scan_fused_kernel<<<dim3(8, B), 384>>>(h0, bha, bhm, label, slen, T, C, k);
    }
    final_kernel<<<1, 32>>>(out, B);
}